// round 5
// baseline (speedup 1.0000x reference)
#include <cuda_runtime.h>

#define NN 50000
#define EE 800000
#define HCH 64
#define ECH 32
#define NHD 4
#define PH 16

// Scratch (device globals; no allocation allowed). 16B-aligned for float4/red.v4.
__device__ __align__(16) float g_K [NN * HCH];   // per-node keys   (n, h, 16)
__device__ __align__(16) float g_V [NN * HCH];   // per-node values (n, h, 16)
__device__ __align__(16) float g_Qt[NN * HCH];   // q~ = wkl^T q    (n, h, 16)
__device__ __align__(16) float g_Qb[NN * NHD];   // q . wkl_b       (n, h)
__device__ __align__(16) float g_U [NN * HCH];   // atomic accum:   sum_e e * W_v * v_col
__device__ __align__(16) float g_D [NN * NHD];   // atomic accum:   sum_e e
__device__ int g_idx64;                          // 1 if edge_index is int64

__device__ __forceinline__ float ssp(float v) {
    // softplus(v) - ln 2, numerically stable
    return fmaxf(v, 0.f) + log1pf(__expf(-fabsf(v))) - 0.69314718055994531f;
}

__device__ __forceinline__ void ld16(const float* __restrict__ p, float* r) {
#pragma unroll
    for (int i = 0; i < 4; i++) {
        float4 v = reinterpret_cast<const float4*>(p)[i];
        r[4*i+0] = v.x; r[4*i+1] = v.y; r[4*i+2] = v.z; r[4*i+3] = v.w;
    }
}

__device__ __forceinline__ void st16(float* p, const float* r) {
#pragma unroll
    for (int i = 0; i < 4; i++) {
        reinterpret_cast<float4*>(p)[i] =
            make_float4(r[4*i+0], r[4*i+1], r[4*i+2], r[4*i+3]);
    }
}

__device__ __forceinline__ void red_add4(float* p, float a, float b, float c, float d) {
    asm volatile("red.global.add.v4.f32 [%0], {%1,%2,%3,%4};"
                 :: "l"(__cvta_generic_to_global(p)),
                    "f"(a), "f"(b), "f"(c), "f"(d) : "memory");
}

// ---------------------------------------------------------------------------
// Kernel 0: detect edge_index element width. If the data is int64 (values are
// node ids < 50000, nonnegative), every high 32-bit word is zero. If the data
// is int32, the sampled words are random node ids (P[all zero] ~ 0).
// ---------------------------------------------------------------------------
__global__ void k_detect(const int* __restrict__ ei_w) {
    int all0 = 1;
    for (int i = 0; i < 256; i++)
        if (ei_w[2 * i + 1] != 0) { all0 = 0; break; }
    g_idx64 = all0;
}

// ---------------------------------------------------------------------------
// Kernel 1: per-(node, head) precompute K, V, Q~ = wkl^T q, qb = q.wkl_b.
// Also zeroes the atomic accumulators.
// ---------------------------------------------------------------------------
__global__ __launch_bounds__(256)
void k_nodes(const float* __restrict__ x,
             const float* __restrict__ kw, const float* __restrict__ qw,
             const float* __restrict__ vw,
             const float* __restrict__ wklw, const float* __restrict__ wklb) {
    __shared__ float s_k[1024], s_q[1024], s_v[1024], s_l[256], s_lb[16];
    for (int i = threadIdx.x; i < 1024; i += 256) {
        s_k[i] = kw[i]; s_q[i] = qw[i]; s_v[i] = vw[i];
    }
    if (threadIdx.x < 256) s_l[threadIdx.x] = wklw[threadIdx.x];
    if (threadIdx.x < 16)  s_lb[threadIdx.x] = wklb[threadIdx.x];
    __syncthreads();

    int t = blockIdx.x * 256 + threadIdx.x;
    if (t >= NN * NHD) return;
    int n = t >> 2, h = t & 3;

    float xv[PH];
    ld16(x + (size_t)n * HCH + h * PH, xv);

    const float* wkh = s_k + h * 256;
    const float* wqh = s_q + h * 256;
    const float* wvh = s_v + h * 256;

    float kk[PH], vv[PH], qq[PH];
#pragma unroll
    for (int o = 0; o < PH; o++) {
        float a = 0.f, b = 0.f, c = 0.f;
#pragma unroll
        for (int i = 0; i < PH; i++) {
            a += xv[i] * wkh[o * PH + i];
            b += xv[i] * wqh[o * PH + i];
            c += xv[i] * wvh[o * PH + i];
        }
        kk[o] = a; qq[o] = b; vv[o] = c;
    }

    float qt[PH];
#pragma unroll
    for (int i = 0; i < PH; i++) {
        float a = 0.f;
#pragma unroll
        for (int o = 0; o < PH; o++) a += qq[o] * s_l[o * PH + i];
        qt[i] = a;
    }
    float qb = 0.f;
#pragma unroll
    for (int o = 0; o < PH; o++) qb += qq[o] * s_lb[o];

    st16(g_K  + (size_t)t * PH, kk);
    st16(g_V  + (size_t)t * PH, vv);
    st16(g_Qt + (size_t)t * PH, qt);
    g_Qb[t] = qb;

    // zero accumulators
    float4 z = make_float4(0.f, 0.f, 0.f, 0.f);
#pragma unroll
    for (int i = 0; i < 4; i++)
        reinterpret_cast<float4*>(g_U + (size_t)t * PH)[i] = z;
    g_D[t] = 0.f;
}

// ---------------------------------------------------------------------------
// Kernel 2: single edge pass.
//   W_k = MLP_k(edge_attr), W_v = MLP_v(edge_attr)
//   per head: s = qb_row + sum_i W_k[i]*K_col[i]*Qt_row[i]; e = exp(s)
//             D[row,h]   += e
//             U[row,h,i] += e * W_v[i] * V_col[i]
// ---------------------------------------------------------------------------
__global__ __launch_bounds__(256)
void k_edges(const int* __restrict__ ei, const float* __restrict__ ea,
             const float* __restrict__ wk1, const float* __restrict__ bk1,
             const float* __restrict__ wk2, const float* __restrict__ bk2,
             const float* __restrict__ wv1, const float* __restrict__ bv1,
             const float* __restrict__ wv2, const float* __restrict__ bv2) {
    __shared__ float s_wk1[512], s_wv1[512], s_wk2[256], s_wv2[256];
    __shared__ float s_bk1[16], s_bk2[16], s_bv1[16], s_bv2[16];
    for (int i = threadIdx.x; i < 512; i += 256) { s_wk1[i] = wk1[i]; s_wv1[i] = wv1[i]; }
    if (threadIdx.x < 256) { s_wk2[threadIdx.x] = wk2[threadIdx.x]; s_wv2[threadIdx.x] = wv2[threadIdx.x]; }
    if (threadIdx.x < 16) {
        s_bk1[threadIdx.x] = bk1[threadIdx.x]; s_bk2[threadIdx.x] = bk2[threadIdx.x];
        s_bv1[threadIdx.x] = bv1[threadIdx.x]; s_bv2[threadIdx.x] = bv2[threadIdx.x];
    }
    __syncthreads();

    int e = blockIdx.x * 256 + threadIdx.x;
    if (e >= EE) return;

    int row, col;
    if (g_idx64) {
        const long long* p = (const long long*)ei;
        row = (int)p[e];
        col = (int)p[(size_t)EE + e];
    } else {
        row = ei[e];
        col = ei[EE + e];
    }

    float eav[ECH];
#pragma unroll
    for (int i = 0; i < 8; i++) {
        float4 v = reinterpret_cast<const float4*>(ea + (size_t)e * ECH)[i];
        eav[4*i+0] = v.x; eav[4*i+1] = v.y; eav[4*i+2] = v.z; eav[4*i+3] = v.w;
    }

    // layer 1 (both nets share the input)
    float tk[PH], tv[PH];
#pragma unroll
    for (int j = 0; j < PH; j++) {
        float a = s_bk1[j], b = s_bv1[j];
#pragma unroll
        for (int i = 0; i < ECH; i++) {
            a += eav[i] * s_wk1[j * ECH + i];
            b += eav[i] * s_wv1[j * ECH + i];
        }
        tk[j] = ssp(a); tv[j] = ssp(b);
    }
    // layer 2
    float wkv[PH], wvv[PH];
#pragma unroll
    for (int o = 0; o < PH; o++) {
        float a = s_bk2[o], b = s_bv2[o];
#pragma unroll
        for (int j = 0; j < PH; j++) {
            a += tk[j] * s_wk2[o * PH + j];
            b += tv[j] * s_wv2[o * PH + j];
        }
        wkv[o] = a; wvv[o] = b;
    }

    const float* Kc = g_K  + (size_t)col * HCH;
    const float* Vc = g_V  + (size_t)col * HCH;
    const float* Qt = g_Qt + (size_t)row * HCH;
    float*       Up = g_U  + (size_t)row * HCH;

#pragma unroll
    for (int h = 0; h < NHD; h++) {
        float kr[PH], qr[PH];
        ld16(Kc + h * PH, kr);
        ld16(Qt + h * PH, qr);
        float s = g_Qb[row * NHD + h];
#pragma unroll
        for (int i = 0; i < PH; i++) s += (wkv[i] * kr[i]) * qr[i];
        float eh = __expf(s);
        atomicAdd(&g_D[row * NHD + h], eh);

        float vr[PH];
        ld16(Vc + h * PH, vr);
#pragma unroll
        for (int q = 0; q < 4; q++) {
            red_add4(Up + h * PH + 4 * q,
                     eh * wvv[4*q+0] * vr[4*q+0],
                     eh * wvv[4*q+1] * vr[4*q+1],
                     eh * wvv[4*q+2] * vr[4*q+2],
                     eh * wvv[4*q+3] * vr[4*q+3]);
        }
    }
}

// ---------------------------------------------------------------------------
// Kernel 3: per node — aggr = (wvl @ U)/D + wvl_b (if D>0), then
//   y = out_w @ ssp(cen_w @ x + cen_b + aggr) + out_b
// blockDim = (64 out-channels, 8 nodes)
// ---------------------------------------------------------------------------
#define NB3 8
__global__ __launch_bounds__(512)
void k_out(const float* __restrict__ x,
           const float* __restrict__ wvlw, const float* __restrict__ wvlb,
           const float* __restrict__ cenw, const float* __restrict__ cenb,
           const float* __restrict__ outw, const float* __restrict__ outb,
           float* __restrict__ y) {
    __shared__ float s_cen[64 * 65], s_out[64 * 65];   // padded (bank-conflict-free)
    __shared__ float s_wvl[16 * 17];
    __shared__ float s_cb[64], s_ob[64], s_vb[16];
    __shared__ float s_t[NB3][64];

    int tid = threadIdx.y * 64 + threadIdx.x;
    for (int idx = tid; idx < 4096; idx += 512) {
        int o = idx >> 6, i = idx & 63;
        s_cen[o * 65 + i] = cenw[idx];
        s_out[o * 65 + i] = outw[idx];
    }
    if (tid < 256) { int oo = tid >> 4, i = tid & 15; s_wvl[oo * 17 + i] = wvlw[tid]; }
    if (tid < 64) { s_cb[tid] = cenb[tid]; s_ob[tid] = outb[tid]; }
    if (tid < 16) s_vb[tid] = wvlb[tid];
    __syncthreads();

    int o = threadIdx.x;
    int n = blockIdx.x * NB3 + threadIdx.y;
    bool valid = n < NN;
    int nc = valid ? n : (NN - 1);
    int h = o >> 4, oo = o & 15;

    float dd = g_D[nc * NHD + h];
    const float* u = g_U + (size_t)nc * HCH + h * PH;
    float a = 0.f;
#pragma unroll
    for (int i = 0; i < PH; i++) a += s_wvl[oo * 17 + i] * u[i];
    a = (dd > 0.f) ? (a / dd + s_vb[oo]) : 0.f;

    const float* xr = x + (size_t)nc * HCH;
    float c = s_cb[o];
#pragma unroll
    for (int i = 0; i < 64; i++) c += s_cen[o * 65 + i] * xr[i];

    s_t[threadIdx.y][o] = ssp(c + a);
    __syncthreads();

    float yy = s_ob[o];
#pragma unroll
    for (int i = 0; i < 64; i++) yy += s_out[o * 65 + i] * s_t[threadIdx.y][i];

    if (valid) y[(size_t)n * HCH + o] = yy;
}

// ---------------------------------------------------------------------------
extern "C" void kernel_launch(void* const* d_in, const int* in_sizes, int n_in,
                              void* d_out, int out_size) {
    const float* x    = (const float*)d_in[0];
    const int*   ei   = (const int*)d_in[1];
    const float* ea   = (const float*)d_in[2];
    const float* kw   = (const float*)d_in[3];
    const float* qw   = (const float*)d_in[4];
    const float* vw   = (const float*)d_in[5];
    const float* wk1  = (const float*)d_in[6];
    const float* bk1  = (const float*)d_in[7];
    const float* wk2  = (const float*)d_in[8];
    const float* bk2  = (const float*)d_in[9];
    const float* wklw = (const float*)d_in[10];
    const float* wklb = (const float*)d_in[11];
    const float* wv1  = (const float*)d_in[12];
    const float* bv1  = (const float*)d_in[13];
    const float* wv2  = (const float*)d_in[14];
    const float* bv2  = (const float*)d_in[15];
    const float* wvlw = (const float*)d_in[16];
    const float* wvlb = (const float*)d_in[17];
    const float* cenw = (const float*)d_in[18];
    const float* cenb = (const float*)d_in[19];
    const float* outw = (const float*)d_in[20];
    const float* outb = (const float*)d_in[21];
    float* out = (float*)d_out;

    k_detect<<<1, 1>>>(ei);
    k_nodes<<<(NN * NHD + 255) / 256, 256>>>(x, kw, qw, vw, wklw, wklb);
    k_edges<<<(EE + 255) / 256, 256>>>(ei, ea, wk1, bk1, wk2, bk2,
                                       wv1, bv1, wv2, bv2);
    k_out<<<(NN + NB3 - 1) / NB3, dim3(64, NB3)>>>(x, wvlw, wvlb, cenw, cenb,
                                                   outw, outb, out);
}